// round 10
// baseline (speedup 1.0000x reference)
#include <cuda_runtime.h>
#include <math.h>

// ---------------- problem dims (fixed) ----------------
#define BN_EPS 1e-5f
#define SIGMA  1.0f
#define BB   8
#define IC1  128
#define H1   64
#define W1   64
#define OC1  64
#define OH1  32
#define OW1  32
#define IC2  64
#define OC2  32
#define OH2  16
#define OW2  16
#define KK   6
#define NELEM (BB*IC1*H1*W1)          // 4194304 per output plane
#define L2E  1.4426950408889634f

// ---------------- scratch (no allocations allowed) ----------------
__device__ float g_o1p[4*BB*OC1*OH1*OW1];  // conv1 partial sums (4 ic-quarters)
__device__ float g_o2[BB*OC2*OH2*OW2];     // conv2 output (8,32,16,16)
__device__ float g_centers[BB*KK];         // (8,6)

// ---------------- packed f32x2 helpers ----------------
__device__ __forceinline__ void fma2(unsigned long long &d,
                                     unsigned long long a,
                                     unsigned long long b) {
    asm("fma.rn.f32x2 %0, %1, %2, %0;" : "+l"(d) : "l"(a), "l"(b));
}
__device__ __forceinline__ unsigned long long dup2(float x) {
    unsigned long long d;
    asm("mov.b64 %0, {%1, %1};" : "=l"(d) : "f"(x));
    return d;
}
__device__ __forceinline__ void unpack2(unsigned long long v, float &lo, float &hi) {
    asm("mov.b64 {%0, %1}, %2;" : "=f"(lo), "=f"(hi) : "l"(v));
}
__device__ __forceinline__ float ex2f(float x) {
    float r;
    asm("ex2.approx.ftz.f32 %0, %1;" : "=f"(r) : "f"(x));
    return r;
}

// =====================================================================
// conv1: (8,128,64,64) --3x3 s2 p1--> partial sums, NO BN/ReLU here.
// grid (32 oh, 8 b, 4 icq), 128 threads. thread = 4 oc x 4 ow via
// f32x2 oc-pairs. Each block sums 32 input channels (4 chunks of 8).
// Weights in smem [icl][tap][pair(32)] -> conflict-free LDS.64.
// =====================================================================
#define C1_ICH 8

__global__ __launch_bounds__(128) void conv1_kernel(
    const float* __restrict__ cf, const float* __restrict__ w1)
{
    __shared__ float  s_in[3*C1_ICH*68];            // [rr][ic][68]
    __shared__ float2 s_w[C1_ICH*9*32];             // [icl][tap][pair(32)]

    const int t   = threadIdx.x;
    const int oh  = blockIdx.x;
    const int b   = blockIdx.y;
    const int icq = blockIdx.z;
    const int owg = t & 7;          // ow base = 4*owg
    const int ocg = t >> 3;         // oc base = 4*ocg (pairs 2*ocg, 2*ocg+1)
    const int p0  = ocg * 2;

    unsigned long long acc[2][4];
#pragma unroll
    for (int p = 0; p < 2; p++)
#pragma unroll
        for (int j = 0; j < 4; j++) acc[p][j] = 0ull;

    const float* cfb = cf + (size_t)b * IC1 * H1 * W1;
    const int gr0 = 2*oh - 1;
    const int icbase = icq * 32;

    for (int cc = 0; cc < 4; cc++) {
        const int ic0 = icbase + cc * C1_ICH;
        // ---- stage input rows [gr0..gr0+2], cols -1..64 zero-padded ----
        for (int idx = t; idx < 3*C1_ICH*68; idx += 128) {
            const int c   = idx % 68;
            const int rem = idx / 68;
            const int icl = rem % C1_ICH;
            const int rr  = rem / C1_ICH;
            const int gr  = gr0 + rr;
            float v = 0.f;
            if (gr >= 0 && gr < H1 && c >= 1 && c <= 64)
                v = cfb[((size_t)(ic0 + icl) * H1 + gr) * W1 + (c - 1)];
            s_in[idx] = v;
        }
        // ---- stage weights: [icl][tap][pair], pair fastest ----
        for (int idx = t; idx < C1_ICH*9*32; idx += 128) {
            const int pair = idx & 31;
            const int r    = idx >> 5;
            const int tap  = r % 9;
            const int icl  = r / 9;
            const int oc   = 2 * pair;
            const int gic  = ic0 + icl;
            s_w[(icl*9 + tap)*32 + pair] =
                make_float2(w1[((size_t)oc*IC1 + gic)*9 + tap],
                            w1[((size_t)(oc+1)*IC1 + gic)*9 + tap]);
        }
        __syncthreads();

        for (int icl = 0; icl < C1_ICH; icl++) {
            const unsigned long long* wic =
                (const unsigned long long*)&s_w[(icl*9)*32];
#pragma unroll
            for (int rr = 0; rr < 3; rr++) {
                const float* xp = &s_in[(rr*C1_ICH + icl)*68 + 8*owg];
                const float4 xa = *(const float4*)(xp);
                const float4 xb = *(const float4*)(xp + 4);
                const float  xc = xp[8];
                unsigned long long xd[9];
                xd[0] = dup2(xa.x); xd[1] = dup2(xa.y); xd[2] = dup2(xa.z); xd[3] = dup2(xa.w);
                xd[4] = dup2(xb.x); xd[5] = dup2(xb.y); xd[6] = dup2(xb.z); xd[7] = dup2(xb.w);
                xd[8] = dup2(xc);
#pragma unroll
                for (int p = 0; p < 2; p++) {
                    const unsigned long long w0  = wic[(rr*3 + 0)*32 + p0 + p];
                    const unsigned long long w1v = wic[(rr*3 + 1)*32 + p0 + p];
                    const unsigned long long w2v = wic[(rr*3 + 2)*32 + p0 + p];
#pragma unroll
                    for (int j = 0; j < 4; j++) {
                        fma2(acc[p][j], w0,  xd[2*j + 0]);
                        fma2(acc[p][j], w1v, xd[2*j + 1]);
                        fma2(acc[p][j], w2v, xd[2*j + 2]);
                    }
                }
            }
        }
        __syncthreads();
    }

    // ---- write partials: g_o1p[icq][b][oc][oh][ow] ----
    float* op = g_o1p + (size_t)icq * (BB*OC1*OH1*OW1)
                      + (((size_t)b*OC1)*OH1 + oh)*OW1;
#pragma unroll
    for (int p = 0; p < 2; p++) {
        float lo0, hi0, lo1, hi1, lo2, hi2, lo3, hi3;
        unpack2(acc[p][0], lo0, hi0);
        unpack2(acc[p][1], lo1, hi1);
        unpack2(acc[p][2], lo2, hi2);
        unpack2(acc[p][3], lo3, hi3);
        const int ocA = 4*ocg + 2*p;
        *(float4*)(op + (size_t)ocA     * (OH1*OW1) + 4*owg) = make_float4(lo0, lo1, lo2, lo3);
        *(float4*)(op + (size_t)(ocA+1) * (OH1*OW1) + 4*owg) = make_float4(hi0, hi1, hi2, hi3);
    }
}

// =====================================================================
// conv2: sum 4 partials -> BN1 -> ReLU -> 3x3 s2 conv -> BN2 -> ReLU
// grid (16 oh, 8 b), 256 threads. thread = 1 oc-pair x 1 ow (f32x2).
// Weights in smem [icl][tap][pair(16)] -> conflict-free.
// =====================================================================
#define C2_ICH 16
#define O1PLANE (BB*OC1*OH1*OW1)

__global__ __launch_bounds__(256) void conv2_kernel(
    const float* __restrict__ w2,
    const float* __restrict__ g1, const float* __restrict__ b1,
    const float* __restrict__ m1, const float* __restrict__ v1,
    const float* __restrict__ g2, const float* __restrict__ b2,
    const float* __restrict__ m2, const float* __restrict__ v2)
{
    __shared__ float  s_in[3*C2_ICH*36];     // [rr][ic][36]
    __shared__ float2 s_w[C2_ICH*9*16];      // [icl][tap][pair(16)]
    __shared__ float  s_inv1[IC2], s_bias1[IC2];

    const int t   = threadIdx.x;
    const int oh  = blockIdx.x;
    const int b   = blockIdx.y;
    const int ow  = t & 15;
    const int ocp = t >> 4;          // 0..15 -> oc = 2*ocp, 2*ocp+1

    if (t < IC2) {
        const float inv = g1[t] * rsqrtf(v1[t] + BN_EPS);
        s_inv1[t]  = inv;
        s_bias1[t] = b1[t] - m1[t]*inv;
    }
    __syncthreads();

    unsigned long long acc = 0ull;
    const int gr0 = 2*oh - 1;
    const size_t bofs = ((size_t)b * OC1) * (OH1*OW1);

    for (int cc = 0; cc < 4; cc++) {
        const int ic0 = cc * C2_ICH;
        // ---- stage input: sum partials + BN1 + ReLU, zero-padded ----
        for (int idx = t; idx < 3*C2_ICH*36; idx += 256) {
            const int c   = idx % 36;
            const int rem = idx / 36;
            const int icl = rem % C2_ICH;
            const int rr  = rem / C2_ICH;
            const int gr  = gr0 + rr;
            float v = 0.f;
            if (gr >= 0 && gr < OH1 && c >= 1 && c <= 32) {
                const int gic = ic0 + icl;
                const size_t ofs = bofs + (size_t)gic*(OH1*OW1) + (size_t)gr*OW1 + (c-1);
                float s = g_o1p[ofs] + g_o1p[O1PLANE + ofs]
                        + g_o1p[2*(size_t)O1PLANE + ofs] + g_o1p[3*(size_t)O1PLANE + ofs];
                v = fmaxf(fmaf(s, s_inv1[gic], s_bias1[gic]), 0.f);
            }
            s_in[idx] = v;
        }
        // ---- stage weights: [icl][tap][pair] ----
        for (int idx = t; idx < C2_ICH*9*16; idx += 256) {
            const int pair = idx & 15;
            const int r    = idx >> 4;
            const int tap  = r % 9;
            const int icl  = r / 9;
            const int oc   = 2 * pair;
            const int gic  = ic0 + icl;
            s_w[(icl*9 + tap)*16 + pair] =
                make_float2(w2[((size_t)oc*IC2 + gic)*9 + tap],
                            w2[((size_t)(oc+1)*IC2 + gic)*9 + tap]);
        }
        __syncthreads();

        for (int icl = 0; icl < C2_ICH; icl++) {
            const unsigned long long* wic =
                (const unsigned long long*)&s_w[(icl*9)*16];
#pragma unroll
            for (int rr = 0; rr < 3; rr++) {
                const float* xp = &s_in[(rr*C2_ICH + icl)*36 + 2*ow];
#pragma unroll
                for (int kk = 0; kk < 3; kk++)
                    fma2(acc, wic[(rr*3 + kk)*16 + ocp], dup2(xp[kk]));
            }
        }
        __syncthreads();
    }

    float alo, ahi;
    unpack2(acc, alo, ahi);
    float* o2b = g_o2 + (size_t)b * OC2 * OH2 * OW2;
    {
        const int oc = 2*ocp;
        const float inv  = g2[oc] * rsqrtf(v2[oc] + BN_EPS);
        const float bias = b2[oc] - m2[oc]*inv;
        o2b[((size_t)oc*OH2 + oh)*OW2 + ow] = fmaxf(fmaf(alo, inv, bias), 0.f);
    }
    {
        const int oc = 2*ocp + 1;
        const float inv  = g2[oc] * rsqrtf(v2[oc] + BN_EPS);
        const float bias = b2[oc] - m2[oc]*inv;
        o2b[((size_t)oc*OH2 + oh)*OW2 + ow] = fmaxf(fmaf(ahi, inv, bias), 0.f);
    }
}

// =====================================================================
// conv3 (1x1) + BN + spatial mean, fused analytically. 8 blocks x 256.
// =====================================================================
__global__ __launch_bounds__(256) void conv3_kernel(
    const float* __restrict__ w3,
    const float* __restrict__ g3, const float* __restrict__ b3,
    const float* __restrict__ m3, const float* __restrict__ v3,
    float* __restrict__ out)
{
    __shared__ float s_mean[OC2];
    const int t = threadIdx.x;
    const int b = blockIdx.x;
    const int c    = t >> 3;   // 0..31
    const int part = t & 7;    // 0..7

    const float* p = g_o2 + ((size_t)b*OC2 + c) * (OH2*OW2);
    float s = 0.f;
#pragma unroll
    for (int i = 0; i < 32; i++) s += p[part*32 + i];
    s += __shfl_down_sync(0xffffffffu, s, 4, 8);
    s += __shfl_down_sync(0xffffffffu, s, 2, 8);
    s += __shfl_down_sync(0xffffffffu, s, 1, 8);
    if (part == 0) s_mean[c] = s * (1.f/256.f);
    __syncthreads();

    if (t < KK) {
        float a = 0.f;
#pragma unroll
        for (int c2 = 0; c2 < OC2; c2++)
            a = fmaf(w3[t*OC2 + c2], s_mean[c2], a);
        const float inv = g3[t] * rsqrtf(v3[t] + BN_EPS);
        const float ctr = fmaf(a, inv, b3[t] - m3[t]*inv);
        g_centers[b*KK + t] = ctr;
        out[(size_t)4*NELEM + b*KK + t] = ctr;
    }
}

// =====================================================================
// quantizer, algebraic form (4 elems/thread — coalesced stores):
//   t_k = (2 c_k x - c_k^2) * log2(e);  e_k = 2^{t_k}
//   softmax(-d) == e_k / sum(e)   (exp(x^2) factor cancels)
//   argmin d == argmax t  (strict >, keeps first occurrence)
// grid (512, 8 b), 256 threads, float4 per thread.
// =====================================================================
__global__ __launch_bounds__(256) void quant_kernel(
    const float* __restrict__ x, float* __restrict__ out)
{
    const int b  = blockIdx.y;
    const int i4 = blockIdx.x * 256 + threadIdx.x;
    const size_t base = (size_t)b * (IC1*H1*W1) + (size_t)i4 * 4;

    float c[KK], ak[KK], bk[KK];
#pragma unroll
    for (int k = 0; k < KK; k++) {
        c[k]  = g_centers[b*KK + k];
        ak[k] = 2.f * c[k] * L2E;
        bk[k] = -c[k] * c[k] * L2E;
    }

    const float4 xv = *(const float4*)(x + base);
    const float xe[4] = {xv.x, xv.y, xv.z, xv.w};
    float rb[4], rs[4], rh[4], rsy[4];

#pragma unroll
    for (int e = 0; e < 4; e++) {
        const float xx = xe[e];
        float tm  = fmaf(ak[0], xx, bk[0]);
        float ch  = c[0];
        float sy  = 0.f;
        float e0  = ex2f(tm);
        float sum = e0;
        float ws  = e0 * c[0];
#pragma unroll
        for (int k = 1; k < KK; k++) {
            const float tk = fmaf(ak[k], xx, bk[k]);
            const float ek = ex2f(tk);
            sum += ek;
            ws   = fmaf(ek, c[k], ws);
            if (tk > tm) { tm = tk; sy = (float)k; ch = c[k]; }
        }
        const float qsoft = __fdividef(ws, sum);
        rb[e]  = qsoft + (ch - qsoft);
        rs[e]  = qsoft;
        rh[e]  = ch;
        rsy[e] = sy;
    }

    *(float4*)(out + 0*(size_t)NELEM + base) = make_float4(rb[0], rb[1], rb[2], rb[3]);
    *(float4*)(out + 1*(size_t)NELEM + base) = make_float4(rs[0], rs[1], rs[2], rs[3]);
    *(float4*)(out + 2*(size_t)NELEM + base) = make_float4(rh[0], rh[1], rh[2], rh[3]);
    *(float4*)(out + 3*(size_t)NELEM + base) = make_float4(rsy[0], rsy[1], rsy[2], rsy[3]);
}

// =====================================================================
// launch — input order per setup_inputs():
// 0:x 1:center_features 2:w1 3:g1 4:b1 5:m1 6:v1 7:w2 8:g2 9:b2 10:m2 11:v2
// 12:w3 13:g3 14:b3 15:m3 16:v3
// =====================================================================
extern "C" void kernel_launch(void* const* d_in, const int* in_sizes, int n_in,
                              void* d_out, int out_size)
{
    (void)in_sizes; (void)n_in; (void)out_size;
    const float* x  = (const float*)d_in[0];
    const float* cf = (const float*)d_in[1];
    const float* w1 = (const float*)d_in[2];
    const float* g1 = (const float*)d_in[3];
    const float* b1 = (const float*)d_in[4];
    const float* m1 = (const float*)d_in[5];
    const float* v1 = (const float*)d_in[6];
    const float* w2 = (const float*)d_in[7];
    const float* g2 = (const float*)d_in[8];
    const float* b2 = (const float*)d_in[9];
    const float* m2 = (const float*)d_in[10];
    const float* v2 = (const float*)d_in[11];
    const float* w3 = (const float*)d_in[12];
    const float* g3 = (const float*)d_in[13];
    const float* b3 = (const float*)d_in[14];
    const float* m3 = (const float*)d_in[15];
    const float* v3 = (const float*)d_in[16];
    float* out = (float*)d_out;

    conv1_kernel<<<dim3(OH1, BB, 4), 128>>>(cf, w1);
    conv2_kernel<<<dim3(OH2, BB), 256>>>(w2, g1, b1, m1, v1, g2, b2, m2, v2);
    conv3_kernel<<<BB, 256>>>(w3, g3, b3, m3, v3, out);
    quant_kernel<<<dim3(512, BB), 256>>>(x, out);
}

// round 11
// speedup vs baseline: 1.5650x; 1.5650x over previous
#include <cuda_runtime.h>
#include <math.h>

// ---------------- problem dims (fixed) ----------------
#define BN_EPS 1e-5f
#define SIGMA  1.0f
#define BB   8
#define IC1  128
#define H1   64
#define W1   64
#define OC1  64
#define OH1  32
#define OW1  32
#define IC2  64
#define OC2  32
#define OH2  16
#define OW2  16
#define KK   6
#define NELEM (BB*IC1*H1*W1)          // 4194304 per output plane
#define L2E  1.4426950408889634f
#define NQ   8                        // ic-split factor for conv1

// ---------------- scratch (no allocations allowed) ----------------
__device__ float g_o1p[NQ*BB*OC1*OH1*OW1]; // conv1 partial sums (8 ic-eighths)
__device__ float g_o2[BB*OC2*OH2*OW2];     // conv2 output (8,32,16,16)
__device__ float g_centers[BB*KK];         // (8,6)

// ---------------- packed f32x2 helpers ----------------
__device__ __forceinline__ void fma2(unsigned long long &d,
                                     unsigned long long a,
                                     unsigned long long b) {
    asm("fma.rn.f32x2 %0, %1, %2, %0;" : "+l"(d) : "l"(a), "l"(b));
}
__device__ __forceinline__ unsigned long long dup2(float x) {
    unsigned long long d;
    asm("mov.b64 %0, {%1, %1};" : "=l"(d) : "f"(x));
    return d;
}
__device__ __forceinline__ void unpack2(unsigned long long v, float &lo, float &hi) {
    asm("mov.b64 {%0, %1}, %2;" : "=f"(lo), "=f"(hi) : "l"(v));
}
__device__ __forceinline__ float ex2f(float x) {
    float r;
    asm("ex2.approx.ftz.f32 %0, %1;" : "=f"(r) : "f"(x));
    return r;
}

// =====================================================================
// conv1: (8,128,64,64) --3x3 s2 p1--> partial sums, NO BN/ReLU here.
// grid (32 oh, 8 b, 8 icq), 128 threads. thread = 4 oc x 4 ow via
// f32x2 oc-pairs. Each block sums 16 input channels (2 chunks of 8).
// R5-proven layout; weight pair-stride padded 80->82 float2 (conflict-
// free), x rows padded col -> col + 4*(col>>3) (conflict-free LDS.128).
// =====================================================================
#define C1_ICH 8
#define C1_XSTR 100                   // padded x row stride (floats)
#define C1_WSTR 82                    // padded weight pair stride (float2)

__global__ __launch_bounds__(128) void conv1_kernel(
    const float* __restrict__ cf, const float* __restrict__ w1)
{
    __shared__ float  s_in[3*C1_ICH*C1_XSTR];       // [rr][ic][padded 66 cols]
    __shared__ float2 s_w2[32*C1_WSTR];             // [pair][icl*10 + tap]

    const int t   = threadIdx.x;
    const int oh  = blockIdx.x;
    const int b   = blockIdx.y;
    const int icq = blockIdx.z;
    const int owg = t & 7;          // ow base = 4*owg
    const int ocg = t >> 3;         // oc base = 4*ocg (pairs 2*ocg, 2*ocg+1)
    const int p0  = ocg * 2;

    unsigned long long acc[2][4];
#pragma unroll
    for (int p = 0; p < 2; p++)
#pragma unroll
        for (int j = 0; j < 4; j++) acc[p][j] = 0ull;

    const float* cfb = cf + (size_t)b * IC1 * H1 * W1;
    const int gr0 = 2*oh - 1;
    const int icbase = icq * 16;

    for (int cc = 0; cc < 2; cc++) {
        const int ic0 = icbase + cc * C1_ICH;
        // ---- stage input rows [gr0..gr0+2], cols -1..64 zero-padded ----
        for (int idx = t; idx < 3*C1_ICH*66; idx += 128) {
            const int c   = idx % 66;              // c-1 = global col in -1..64
            const int rem = idx / 66;
            const int icl = rem % C1_ICH;
            const int rr  = rem / C1_ICH;
            const int gr  = gr0 + rr;
            float v = 0.f;
            if (gr >= 0 && gr < H1 && c >= 1 && c <= 64)
                v = cfb[((size_t)(ic0 + icl) * H1 + gr) * W1 + (c - 1)];
            s_in[(rr*C1_ICH + icl)*C1_XSTR + c + 4*(c >> 3)] = v;
        }
        // ---- stage weights: [pair][icl*10+tap], padded pair stride ----
        for (int idx = t; idx < 32*C1_ICH*9; idx += 128) {
            const int r    = idx % (C1_ICH*9);
            const int pair = idx / (C1_ICH*9);
            const int icl  = r / 9;
            const int tap  = r % 9;
            const int oc   = 2 * pair;
            const int gic  = ic0 + icl;
            s_w2[pair*C1_WSTR + icl*10 + tap] =
                make_float2(w1[((size_t)oc*IC1 + gic)*9 + tap],
                            w1[((size_t)(oc+1)*IC1 + gic)*9 + tap]);
        }
        __syncthreads();

#pragma unroll
        for (int icl = 0; icl < C1_ICH; icl++) {
#pragma unroll
            for (int rr = 0; rr < 3; rr++) {
                const float* xp = &s_in[(rr*C1_ICH + icl)*C1_XSTR + 12*owg];
                const float4 xa = *(const float4*)(xp);
                const float4 xb = *(const float4*)(xp + 4);
                const float  xc = xp[12];
                unsigned long long xd[9];
                xd[0] = dup2(xa.x); xd[1] = dup2(xa.y); xd[2] = dup2(xa.z); xd[3] = dup2(xa.w);
                xd[4] = dup2(xb.x); xd[5] = dup2(xb.y); xd[6] = dup2(xb.z); xd[7] = dup2(xb.w);
                xd[8] = dup2(xc);
#pragma unroll
                for (int p = 0; p < 2; p++) {
                    const unsigned long long* wp = (const unsigned long long*)
                        &s_w2[(p0 + p)*C1_WSTR + icl*10 + rr*3];
                    const unsigned long long w0 = wp[0], w1v = wp[1], w2v = wp[2];
#pragma unroll
                    for (int j = 0; j < 4; j++) {
                        fma2(acc[p][j], w0,  xd[2*j + 0]);
                        fma2(acc[p][j], w1v, xd[2*j + 1]);
                        fma2(acc[p][j], w2v, xd[2*j + 2]);
                    }
                }
            }
        }
        __syncthreads();
    }

    // ---- write partials: g_o1p[icq][b][oc][oh][ow] ----
    float* op = g_o1p + (size_t)icq * (BB*OC1*OH1*OW1)
                      + (((size_t)b*OC1)*OH1 + oh)*OW1;
#pragma unroll
    for (int p = 0; p < 2; p++) {
        float lo0, hi0, lo1, hi1, lo2, hi2, lo3, hi3;
        unpack2(acc[p][0], lo0, hi0);
        unpack2(acc[p][1], lo1, hi1);
        unpack2(acc[p][2], lo2, hi2);
        unpack2(acc[p][3], lo3, hi3);
        const int ocA = 4*ocg + 2*p;
        *(float4*)(op + (size_t)ocA     * (OH1*OW1) + 4*owg) = make_float4(lo0, lo1, lo2, lo3);
        *(float4*)(op + (size_t)(ocA+1) * (OH1*OW1) + 4*owg) = make_float4(hi0, hi1, hi2, hi3);
    }
}

// =====================================================================
// conv2: sum 8 partials -> BN1 -> ReLU -> 3x3 s2 conv -> BN2 -> ReLU
// grid (16 oh, 8 b), 256 threads. thread = 1 oc-pair x 1 ow (f32x2).
// Weight pair-stride padded 160 -> 162 float2 (conflict-free).
// =====================================================================
#define C2_ICH 16
#define C2_WSTR 162
#define O1PLANE (BB*OC1*OH1*OW1)

__global__ __launch_bounds__(256) void conv2_kernel(
    const float* __restrict__ w2,
    const float* __restrict__ g1, const float* __restrict__ b1,
    const float* __restrict__ m1, const float* __restrict__ v1,
    const float* __restrict__ g2, const float* __restrict__ b2,
    const float* __restrict__ m2, const float* __restrict__ v2)
{
    __shared__ float  s_in[3*C2_ICH*36];     // [rr][ic][36]
    __shared__ float2 s_w2[16*C2_WSTR];      // [pair][icl*10+tap]
    __shared__ float  s_inv1[IC2], s_bias1[IC2];

    const int t   = threadIdx.x;
    const int oh  = blockIdx.x;
    const int b   = blockIdx.y;
    const int ow  = t & 15;
    const int ocp = t >> 4;          // 0..15 -> oc = 2*ocp, 2*ocp+1

    if (t < IC2) {
        const float inv = g1[t] * rsqrtf(v1[t] + BN_EPS);
        s_inv1[t]  = inv;
        s_bias1[t] = b1[t] - m1[t]*inv;
    }
    __syncthreads();

    unsigned long long acc = 0ull;
    const int gr0 = 2*oh - 1;
    const size_t bofs = ((size_t)b * OC1) * (OH1*OW1);

    for (int cc = 0; cc < 4; cc++) {
        const int ic0 = cc * C2_ICH;
        // ---- stage input: sum 8 partials + BN1 + ReLU, zero-padded ----
        for (int idx = t; idx < 3*C2_ICH*36; idx += 256) {
            const int c   = idx % 36;
            const int rem = idx / 36;
            const int icl = rem % C2_ICH;
            const int rr  = rem / C2_ICH;
            const int gr  = gr0 + rr;
            float v = 0.f;
            if (gr >= 0 && gr < OH1 && c >= 1 && c <= 32) {
                const int gic = ic0 + icl;
                const size_t ofs = bofs + (size_t)gic*(OH1*OW1) + (size_t)gr*OW1 + (c-1);
                float s = 0.f;
#pragma unroll
                for (int q = 0; q < NQ; q++)
                    s += g_o1p[(size_t)q*O1PLANE + ofs];
                v = fmaxf(fmaf(s, s_inv1[gic], s_bias1[gic]), 0.f);
            }
            s_in[idx] = v;
        }
        // ---- stage weights: [pair][icl*10+tap], padded pair stride ----
        for (int idx = t; idx < 16*C2_ICH*9; idx += 256) {
            const int r    = idx % (C2_ICH*9);
            const int pair = idx / (C2_ICH*9);
            const int icl  = r / 9;
            const int tap  = r % 9;
            const int oc   = 2 * pair;
            const int gic  = ic0 + icl;
            s_w2[pair*C2_WSTR + icl*10 + tap] =
                make_float2(w2[((size_t)oc*IC2 + gic)*9 + tap],
                            w2[((size_t)(oc+1)*IC2 + gic)*9 + tap]);
        }
        __syncthreads();

#pragma unroll 4
        for (int icl = 0; icl < C2_ICH; icl++) {
            const unsigned long long* wp = (const unsigned long long*)
                &s_w2[ocp*C2_WSTR + icl*10];
#pragma unroll
            for (int rr = 0; rr < 3; rr++) {
                const float* xp = &s_in[(rr*C2_ICH + icl)*36 + 2*ow];
#pragma unroll
                for (int kk = 0; kk < 3; kk++)
                    fma2(acc, wp[rr*3 + kk], dup2(xp[kk]));
            }
        }
        __syncthreads();
    }

    float alo, ahi;
    unpack2(acc, alo, ahi);
    float* o2b = g_o2 + (size_t)b * OC2 * OH2 * OW2;
    {
        const int oc = 2*ocp;
        const float inv  = g2[oc] * rsqrtf(v2[oc] + BN_EPS);
        const float bias = b2[oc] - m2[oc]*inv;
        o2b[((size_t)oc*OH2 + oh)*OW2 + ow] = fmaxf(fmaf(alo, inv, bias), 0.f);
    }
    {
        const int oc = 2*ocp + 1;
        const float inv  = g2[oc] * rsqrtf(v2[oc] + BN_EPS);
        const float bias = b2[oc] - m2[oc]*inv;
        o2b[((size_t)oc*OH2 + oh)*OW2 + ow] = fmaxf(fmaf(ahi, inv, bias), 0.f);
    }
}

// =====================================================================
// conv3 (1x1) + BN + spatial mean, fused analytically. 8 blocks x 256.
// =====================================================================
__global__ __launch_bounds__(256) void conv3_kernel(
    const float* __restrict__ w3,
    const float* __restrict__ g3, const float* __restrict__ b3,
    const float* __restrict__ m3, const float* __restrict__ v3,
    float* __restrict__ out)
{
    __shared__ float s_mean[OC2];
    const int t = threadIdx.x;
    const int b = blockIdx.x;
    const int c    = t >> 3;   // 0..31
    const int part = t & 7;    // 0..7

    const float* p = g_o2 + ((size_t)b*OC2 + c) * (OH2*OW2);
    float s = 0.f;
#pragma unroll
    for (int i = 0; i < 32; i++) s += p[part*32 + i];
    s += __shfl_down_sync(0xffffffffu, s, 4, 8);
    s += __shfl_down_sync(0xffffffffu, s, 2, 8);
    s += __shfl_down_sync(0xffffffffu, s, 1, 8);
    if (part == 0) s_mean[c] = s * (1.f/256.f);
    __syncthreads();

    if (t < KK) {
        float a = 0.f;
#pragma unroll
        for (int c2 = 0; c2 < OC2; c2++)
            a = fmaf(w3[t*OC2 + c2], s_mean[c2], a);
        const float inv = g3[t] * rsqrtf(v3[t] + BN_EPS);
        const float ctr = fmaf(a, inv, b3[t] - m3[t]*inv);
        g_centers[b*KK + t] = ctr;
        out[(size_t)4*NELEM + b*KK + t] = ctr;
    }
}

// =====================================================================
// quantizer, algebraic form (4 elems/thread — coalesced stores):
//   t_k = (2 c_k x - c_k^2) * log2(e);  e_k = 2^{t_k}
//   softmax(-d) == e_k / sum(e)   (exp(x^2) factor cancels)
//   argmin d == argmax t  (strict >, keeps first occurrence)
// grid (512, 8 b), 256 threads, float4 per thread.
// =====================================================================
__global__ __launch_bounds__(256) void quant_kernel(
    const float* __restrict__ x, float* __restrict__ out)
{
    const int b  = blockIdx.y;
    const int i4 = blockIdx.x * 256 + threadIdx.x;
    const size_t base = (size_t)b * (IC1*H1*W1) + (size_t)i4 * 4;

    float c[KK], ak[KK], bk[KK];
#pragma unroll
    for (int k = 0; k < KK; k++) {
        c[k]  = g_centers[b*KK + k];
        ak[k] = 2.f * c[k] * L2E;
        bk[k] = -c[k] * c[k] * L2E;
    }

    const float4 xv = *(const float4*)(x + base);
    const float xe[4] = {xv.x, xv.y, xv.z, xv.w};
    float rb[4], rs[4], rh[4], rsy[4];

#pragma unroll
    for (int e = 0; e < 4; e++) {
        const float xx = xe[e];
        float tm  = fmaf(ak[0], xx, bk[0]);
        float ch  = c[0];
        float sy  = 0.f;
        float e0  = ex2f(tm);
        float sum = e0;
        float ws  = e0 * c[0];
#pragma unroll
        for (int k = 1; k < KK; k++) {
            const float tk = fmaf(ak[k], xx, bk[k]);
            const float ek = ex2f(tk);
            sum += ek;
            ws   = fmaf(ek, c[k], ws);
            if (tk > tm) { tm = tk; sy = (float)k; ch = c[k]; }
        }
        const float qsoft = __fdividef(ws, sum);
        rb[e]  = qsoft + (ch - qsoft);
        rs[e]  = qsoft;
        rh[e]  = ch;
        rsy[e] = sy;
    }

    *(float4*)(out + 0*(size_t)NELEM + base) = make_float4(rb[0], rb[1], rb[2], rb[3]);
    *(float4*)(out + 1*(size_t)NELEM + base) = make_float4(rs[0], rs[1], rs[2], rs[3]);
    *(float4*)(out + 2*(size_t)NELEM + base) = make_float4(rh[0], rh[1], rh[2], rh[3]);
    *(float4*)(out + 3*(size_t)NELEM + base) = make_float4(rsy[0], rsy[1], rsy[2], rsy[3]);
}

// =====================================================================
// launch — input order per setup_inputs():
// 0:x 1:center_features 2:w1 3:g1 4:b1 5:m1 6:v1 7:w2 8:g2 9:b2 10:m2 11:v2
// 12:w3 13:g3 14:b3 15:m3 16:v3
// =====================================================================
extern "C" void kernel_launch(void* const* d_in, const int* in_sizes, int n_in,
                              void* d_out, int out_size)
{
    (void)in_sizes; (void)n_in; (void)out_size;
    const float* x  = (const float*)d_in[0];
    const float* cf = (const float*)d_in[1];
    const float* w1 = (const float*)d_in[2];
    const float* g1 = (const float*)d_in[3];
    const float* b1 = (const float*)d_in[4];
    const float* m1 = (const float*)d_in[5];
    const float* v1 = (const float*)d_in[6];
    const float* w2 = (const float*)d_in[7];
    const float* g2 = (const float*)d_in[8];
    const float* b2 = (const float*)d_in[9];
    const float* m2 = (const float*)d_in[10];
    const float* v2 = (const float*)d_in[11];
    const float* w3 = (const float*)d_in[12];
    const float* g3 = (const float*)d_in[13];
    const float* b3 = (const float*)d_in[14];
    const float* m3 = (const float*)d_in[15];
    const float* v3 = (const float*)d_in[16];
    float* out = (float*)d_out;

    conv1_kernel<<<dim3(OH1, BB, NQ), 128>>>(cf, w1);
    conv2_kernel<<<dim3(OH2, BB), 256>>>(w2, g1, b1, m1, v1, g2, b2, m2, v2);
    conv3_kernel<<<BB, 256>>>(w3, g3, b3, m3, v3, out);
    quant_kernel<<<dim3(512, BB), 256>>>(x, out);
}

// round 12
// speedup vs baseline: 1.5655x; 1.0003x over previous
#include <cuda_runtime.h>
#include <math.h>

// ---------------- problem dims (fixed) ----------------
#define BN_EPS 1e-5f
#define SIGMA  1.0f
#define BB   8
#define IC1  128
#define H1   64
#define W1   64
#define OC1  64
#define OH1  32
#define OW1  32
#define IC2  64
#define OC2  32
#define OH2  16
#define OW2  16
#define KK   6
#define NELEM (BB*IC1*H1*W1)          // 4194304 per output plane
#define L2E  1.4426950408889634f
#define NQ   8                        // ic-split factor for conv1

// ---------------- scratch (no allocations allowed) ----------------
__device__ float g_o1p[NQ*BB*OC1*OH1*OW1]; // conv1 partial sums (8 ic-eighths)
__device__ float g_o2[BB*OC2*OH2*OW2];     // conv2 output (8,32,16,16)
__device__ float g_centers[BB*KK];         // (8,6)

// ---------------- packed f32x2 helpers ----------------
__device__ __forceinline__ void fma2(unsigned long long &d,
                                     unsigned long long a,
                                     unsigned long long b) {
    asm("fma.rn.f32x2 %0, %1, %2, %0;" : "+l"(d) : "l"(a), "l"(b));
}
__device__ __forceinline__ unsigned long long dup2(float x) {
    unsigned long long d;
    asm("mov.b64 %0, {%1, %1};" : "=l"(d) : "f"(x));
    return d;
}
__device__ __forceinline__ void unpack2(unsigned long long v, float &lo, float &hi) {
    asm("mov.b64 {%0, %1}, %2;" : "=f"(lo), "=f"(hi) : "l"(v));
}
__device__ __forceinline__ float ex2f(float x) {
    float r;
    asm("ex2.approx.ftz.f32 %0, %1;" : "=f"(r) : "f"(x));
    return r;
}

// =====================================================================
// conv1: (8,128,64,64) --3x3 s2 p1--> partial sums, NO BN/ReLU here.
// grid (32 oh, 8 b, 8 icq), 128 threads. thread = 4 oc x 4 ow via
// f32x2 oc-pairs. Each block sums 16 input channels (2 chunks of 8).
// R5-proven layout; weight pair-stride padded 80->82 float2 (conflict-
// free), x rows padded col -> col + 4*(col>>3) (conflict-free LDS.128).
// =====================================================================
#define C1_ICH 8
#define C1_XSTR 100                   // padded x row stride (floats)
#define C1_WSTR 82                    // padded weight pair stride (float2)

__global__ __launch_bounds__(128) void conv1_kernel(
    const float* __restrict__ cf, const float* __restrict__ w1)
{
    __shared__ float  s_in[3*C1_ICH*C1_XSTR];       // [rr][ic][padded 66 cols]
    __shared__ float2 s_w2[32*C1_WSTR];             // [pair][icl*10 + tap]

    const int t   = threadIdx.x;
    const int oh  = blockIdx.x;
    const int b   = blockIdx.y;
    const int icq = blockIdx.z;
    const int owg = t & 7;          // ow base = 4*owg
    const int ocg = t >> 3;         // oc base = 4*ocg (pairs 2*ocg, 2*ocg+1)
    const int p0  = ocg * 2;

    unsigned long long acc[2][4];
#pragma unroll
    for (int p = 0; p < 2; p++)
#pragma unroll
        for (int j = 0; j < 4; j++) acc[p][j] = 0ull;

    const float* cfb = cf + (size_t)b * IC1 * H1 * W1;
    const int gr0 = 2*oh - 1;
    const int icbase = icq * 16;

    for (int cc = 0; cc < 2; cc++) {
        const int ic0 = icbase + cc * C1_ICH;
        // ---- stage input rows [gr0..gr0+2], cols -1..64 zero-padded ----
        for (int idx = t; idx < 3*C1_ICH*66; idx += 128) {
            const int c   = idx % 66;              // c-1 = global col in -1..64
            const int rem = idx / 66;
            const int icl = rem % C1_ICH;
            const int rr  = rem / C1_ICH;
            const int gr  = gr0 + rr;
            float v = 0.f;
            if (gr >= 0 && gr < H1 && c >= 1 && c <= 64)
                v = cfb[((size_t)(ic0 + icl) * H1 + gr) * W1 + (c - 1)];
            s_in[(rr*C1_ICH + icl)*C1_XSTR + c + 4*(c >> 3)] = v;
        }
        // ---- stage weights: [pair][icl*10+tap], padded pair stride ----
        for (int idx = t; idx < 32*C1_ICH*9; idx += 128) {
            const int r    = idx % (C1_ICH*9);
            const int pair = idx / (C1_ICH*9);
            const int icl  = r / 9;
            const int tap  = r % 9;
            const int oc   = 2 * pair;
            const int gic  = ic0 + icl;
            s_w2[pair*C1_WSTR + icl*10 + tap] =
                make_float2(w1[((size_t)oc*IC1 + gic)*9 + tap],
                            w1[((size_t)(oc+1)*IC1 + gic)*9 + tap]);
        }
        __syncthreads();

#pragma unroll
        for (int icl = 0; icl < C1_ICH; icl++) {
#pragma unroll
            for (int rr = 0; rr < 3; rr++) {
                const float* xp = &s_in[(rr*C1_ICH + icl)*C1_XSTR + 12*owg];
                const float4 xa = *(const float4*)(xp);
                const float4 xb = *(const float4*)(xp + 4);
                const float  xc = xp[12];
                unsigned long long xd[9];
                xd[0] = dup2(xa.x); xd[1] = dup2(xa.y); xd[2] = dup2(xa.z); xd[3] = dup2(xa.w);
                xd[4] = dup2(xb.x); xd[5] = dup2(xb.y); xd[6] = dup2(xb.z); xd[7] = dup2(xb.w);
                xd[8] = dup2(xc);
#pragma unroll
                for (int p = 0; p < 2; p++) {
                    const unsigned long long* wp = (const unsigned long long*)
                        &s_w2[(p0 + p)*C1_WSTR + icl*10 + rr*3];
                    const unsigned long long w0 = wp[0], w1v = wp[1], w2v = wp[2];
#pragma unroll
                    for (int j = 0; j < 4; j++) {
                        fma2(acc[p][j], w0,  xd[2*j + 0]);
                        fma2(acc[p][j], w1v, xd[2*j + 1]);
                        fma2(acc[p][j], w2v, xd[2*j + 2]);
                    }
                }
            }
        }
        __syncthreads();
    }

    // ---- write partials: g_o1p[icq][b][oc][oh][ow] ----
    float* op = g_o1p + (size_t)icq * (BB*OC1*OH1*OW1)
                      + (((size_t)b*OC1)*OH1 + oh)*OW1;
#pragma unroll
    for (int p = 0; p < 2; p++) {
        float lo0, hi0, lo1, hi1, lo2, hi2, lo3, hi3;
        unpack2(acc[p][0], lo0, hi0);
        unpack2(acc[p][1], lo1, hi1);
        unpack2(acc[p][2], lo2, hi2);
        unpack2(acc[p][3], lo3, hi3);
        const int ocA = 4*ocg + 2*p;
        *(float4*)(op + (size_t)ocA     * (OH1*OW1) + 4*owg) = make_float4(lo0, lo1, lo2, lo3);
        *(float4*)(op + (size_t)(ocA+1) * (OH1*OW1) + 4*owg) = make_float4(hi0, hi1, hi2, hi3);
    }
}

// =====================================================================
// conv2: sum 8 partials -> BN1 -> ReLU -> 3x3 s2 conv -> BN2 -> ReLU
// grid (16 oh, 8 b), 256 threads. thread = 1 oc-pair x 1 ow (f32x2).
// Weight pair-stride padded 160 -> 162 float2 (conflict-free).
// =====================================================================
#define C2_ICH 16
#define C2_WSTR 162
#define O1PLANE (BB*OC1*OH1*OW1)

__global__ __launch_bounds__(256) void conv2_kernel(
    const float* __restrict__ w2,
    const float* __restrict__ g1, const float* __restrict__ b1,
    const float* __restrict__ m1, const float* __restrict__ v1,
    const float* __restrict__ g2, const float* __restrict__ b2,
    const float* __restrict__ m2, const float* __restrict__ v2)
{
    __shared__ float  s_in[3*C2_ICH*36];     // [rr][ic][36]
    __shared__ float2 s_w2[16*C2_WSTR];      // [pair][icl*10+tap]
    __shared__ float  s_inv1[IC2], s_bias1[IC2];

    const int t   = threadIdx.x;
    const int oh  = blockIdx.x;
    const int b   = blockIdx.y;
    const int ow  = t & 15;
    const int ocp = t >> 4;          // 0..15 -> oc = 2*ocp, 2*ocp+1

    if (t < IC2) {
        const float inv = g1[t] * rsqrtf(v1[t] + BN_EPS);
        s_inv1[t]  = inv;
        s_bias1[t] = b1[t] - m1[t]*inv;
    }
    __syncthreads();

    unsigned long long acc = 0ull;
    const int gr0 = 2*oh - 1;
    const size_t bofs = ((size_t)b * OC1) * (OH1*OW1);

    for (int cc = 0; cc < 4; cc++) {
        const int ic0 = cc * C2_ICH;
        // ---- stage input: sum 8 partials + BN1 + ReLU, zero-padded ----
        for (int idx = t; idx < 3*C2_ICH*36; idx += 256) {
            const int c   = idx % 36;
            const int rem = idx / 36;
            const int icl = rem % C2_ICH;
            const int rr  = rem / C2_ICH;
            const int gr  = gr0 + rr;
            float v = 0.f;
            if (gr >= 0 && gr < OH1 && c >= 1 && c <= 32) {
                const int gic = ic0 + icl;
                const size_t ofs = bofs + (size_t)gic*(OH1*OW1) + (size_t)gr*OW1 + (c-1);
                float s = 0.f;
#pragma unroll
                for (int q = 0; q < NQ; q++)
                    s += g_o1p[(size_t)q*O1PLANE + ofs];
                v = fmaxf(fmaf(s, s_inv1[gic], s_bias1[gic]), 0.f);
            }
            s_in[idx] = v;
        }
        // ---- stage weights: [pair][icl*10+tap], padded pair stride ----
        for (int idx = t; idx < 16*C2_ICH*9; idx += 256) {
            const int r    = idx % (C2_ICH*9);
            const int pair = idx / (C2_ICH*9);
            const int icl  = r / 9;
            const int tap  = r % 9;
            const int oc   = 2 * pair;
            const int gic  = ic0 + icl;
            s_w2[pair*C2_WSTR + icl*10 + tap] =
                make_float2(w2[((size_t)oc*IC2 + gic)*9 + tap],
                            w2[((size_t)(oc+1)*IC2 + gic)*9 + tap]);
        }
        __syncthreads();

#pragma unroll 4
        for (int icl = 0; icl < C2_ICH; icl++) {
            const unsigned long long* wp = (const unsigned long long*)
                &s_w2[ocp*C2_WSTR + icl*10];
#pragma unroll
            for (int rr = 0; rr < 3; rr++) {
                const float* xp = &s_in[(rr*C2_ICH + icl)*36 + 2*ow];
#pragma unroll
                for (int kk = 0; kk < 3; kk++)
                    fma2(acc, wp[rr*3 + kk], dup2(xp[kk]));
            }
        }
        __syncthreads();
    }

    float alo, ahi;
    unpack2(acc, alo, ahi);
    float* o2b = g_o2 + (size_t)b * OC2 * OH2 * OW2;
    {
        const int oc = 2*ocp;
        const float inv  = g2[oc] * rsqrtf(v2[oc] + BN_EPS);
        const float bias = b2[oc] - m2[oc]*inv;
        o2b[((size_t)oc*OH2 + oh)*OW2 + ow] = fmaxf(fmaf(alo, inv, bias), 0.f);
    }
    {
        const int oc = 2*ocp + 1;
        const float inv  = g2[oc] * rsqrtf(v2[oc] + BN_EPS);
        const float bias = b2[oc] - m2[oc]*inv;
        o2b[((size_t)oc*OH2 + oh)*OW2 + ow] = fmaxf(fmaf(ahi, inv, bias), 0.f);
    }
}

// =====================================================================
// conv3 (1x1) + BN + spatial mean, fused analytically. 8 blocks x 256.
// =====================================================================
__global__ __launch_bounds__(256) void conv3_kernel(
    const float* __restrict__ w3,
    const float* __restrict__ g3, const float* __restrict__ b3,
    const float* __restrict__ m3, const float* __restrict__ v3,
    float* __restrict__ out)
{
    __shared__ float s_mean[OC2];
    const int t = threadIdx.x;
    const int b = blockIdx.x;
    const int c    = t >> 3;   // 0..31
    const int part = t & 7;    // 0..7

    const float* p = g_o2 + ((size_t)b*OC2 + c) * (OH2*OW2);
    float s = 0.f;
#pragma unroll
    for (int i = 0; i < 32; i++) s += p[part*32 + i];
    s += __shfl_down_sync(0xffffffffu, s, 4, 8);
    s += __shfl_down_sync(0xffffffffu, s, 2, 8);
    s += __shfl_down_sync(0xffffffffu, s, 1, 8);
    if (part == 0) s_mean[c] = s * (1.f/256.f);
    __syncthreads();

    if (t < KK) {
        float a = 0.f;
#pragma unroll
        for (int c2 = 0; c2 < OC2; c2++)
            a = fmaf(w3[t*OC2 + c2], s_mean[c2], a);
        const float inv = g3[t] * rsqrtf(v3[t] + BN_EPS);
        const float ctr = fmaf(a, inv, b3[t] - m3[t]*inv);
        g_centers[b*KK + t] = ctr;
        out[(size_t)4*NELEM + b*KK + t] = ctr;
    }
}

// =====================================================================
// quantizer, algebraic form (4 elems/thread — coalesced stores):
//   t_k = (2 c_k x - c_k^2) * log2(e);  e_k = 2^{t_k}
//   softmax(-d) == e_k / sum(e)   (exp(x^2) factor cancels)
//   argmin d == argmax t  (strict >, keeps first occurrence)
// grid (512, 8 b), 256 threads, float4 per thread.
// =====================================================================
__global__ __launch_bounds__(256) void quant_kernel(
    const float* __restrict__ x, float* __restrict__ out)
{
    const int b  = blockIdx.y;
    const int i4 = blockIdx.x * 256 + threadIdx.x;
    const size_t base = (size_t)b * (IC1*H1*W1) + (size_t)i4 * 4;

    float c[KK], ak[KK], bk[KK];
#pragma unroll
    for (int k = 0; k < KK; k++) {
        c[k]  = g_centers[b*KK + k];
        ak[k] = 2.f * c[k] * L2E;
        bk[k] = -c[k] * c[k] * L2E;
    }

    const float4 xv = *(const float4*)(x + base);
    const float xe[4] = {xv.x, xv.y, xv.z, xv.w};
    float rb[4], rs[4], rh[4], rsy[4];

#pragma unroll
    for (int e = 0; e < 4; e++) {
        const float xx = xe[e];
        float tm  = fmaf(ak[0], xx, bk[0]);
        float ch  = c[0];
        float sy  = 0.f;
        float e0  = ex2f(tm);
        float sum = e0;
        float ws  = e0 * c[0];
#pragma unroll
        for (int k = 1; k < KK; k++) {
            const float tk = fmaf(ak[k], xx, bk[k]);
            const float ek = ex2f(tk);
            sum += ek;
            ws   = fmaf(ek, c[k], ws);
            if (tk > tm) { tm = tk; sy = (float)k; ch = c[k]; }
        }
        const float qsoft = __fdividef(ws, sum);
        rb[e]  = qsoft + (ch - qsoft);
        rs[e]  = qsoft;
        rh[e]  = ch;
        rsy[e] = sy;
    }

    *(float4*)(out + 0*(size_t)NELEM + base) = make_float4(rb[0], rb[1], rb[2], rb[3]);
    *(float4*)(out + 1*(size_t)NELEM + base) = make_float4(rs[0], rs[1], rs[2], rs[3]);
    *(float4*)(out + 2*(size_t)NELEM + base) = make_float4(rh[0], rh[1], rh[2], rh[3]);
    *(float4*)(out + 3*(size_t)NELEM + base) = make_float4(rsy[0], rsy[1], rsy[2], rsy[3]);
}

// =====================================================================
// launch — input order per setup_inputs():
// 0:x 1:center_features 2:w1 3:g1 4:b1 5:m1 6:v1 7:w2 8:g2 9:b2 10:m2 11:v2
// 12:w3 13:g3 14:b3 15:m3 16:v3
// =====================================================================
extern "C" void kernel_launch(void* const* d_in, const int* in_sizes, int n_in,
                              void* d_out, int out_size)
{
    (void)in_sizes; (void)n_in; (void)out_size;
    const float* x  = (const float*)d_in[0];
    const float* cf = (const float*)d_in[1];
    const float* w1 = (const float*)d_in[2];
    const float* g1 = (const float*)d_in[3];
    const float* b1 = (const float*)d_in[4];
    const float* m1 = (const float*)d_in[5];
    const float* v1 = (const float*)d_in[6];
    const float* w2 = (const float*)d_in[7];
    const float* g2 = (const float*)d_in[8];
    const float* b2 = (const float*)d_in[9];
    const float* m2 = (const float*)d_in[10];
    const float* v2 = (const float*)d_in[11];
    const float* w3 = (const float*)d_in[12];
    const float* g3 = (const float*)d_in[13];
    const float* b3 = (const float*)d_in[14];
    const float* m3 = (const float*)d_in[15];
    const float* v3 = (const float*)d_in[16];
    float* out = (float*)d_out;

    conv1_kernel<<<dim3(OH1, BB, NQ), 128>>>(cf, w1);
    conv2_kernel<<<dim3(OH2, BB), 256>>>(w2, g1, b1, m1, v1, g2, b2, m2, v2);
    conv3_kernel<<<BB, 256>>>(w3, g3, b3, m3, v3, out);
    quant_kernel<<<dim3(512, BB), 256>>>(x, out);
}